// round 6
// baseline (speedup 1.0000x reference)
#include <cuda_runtime.h>
#include <math_constants.h>
#include <stdint.h>

#define BB 4
#define NN 8192
#define CC 3
#define OO 64
#define KK 20
#define NK (NN*KK)            // 163840 edges per batch
#define NEDGES (BB*NK)        // 655360 total edges
#define MCOUNT ((double)NEDGES)

#define HALF_N 4096           // candidates per split
#define BUF_SLOTS 16
#define FLUSH_AT 9            // enter group with <=8 pending, +8 pushes <= 16 slots
#define GRP 8                 // candidates per inner group

// ---------------- device scratch (no allocations allowed) ----------------
__device__ int    g_knn[NEDGES];            // neighbor index per (b,n,k)
__device__ float2 g_part[BB*2*NN*KK];       // partial top-k per (b,half,q)
__device__ double g_m1[6];                  // sum of edge vectors
__device__ double g_m2[21];                 // upper-tri sum of outer products
__device__ float  g_W2[OO*6];               // BN-folded weights
__device__ float  g_shift[OO];              // BN-folded bias

// ---------------- zero accumulators (deterministic each launch) ----------
__global__ void zero_stats_kernel() {
    int t = threadIdx.x;
    if (t < 6)  g_m1[t] = 0.0;
    if (t < 21) g_m2[t] = 0.0;
}

// Branch-free stable insert into ascending register list.
// Key fix vs R5: once the new element is placed, the displaced carry shifts
// UNCONDITIONALLY (flag 'ins'), so equal-distance runs keep their original
// index order (matches jax top_k stability). Inserting +inf is a no-op
// (inf is never strictly less, so 'ins' never sets).
__device__ __forceinline__ void sweep_insert(float* dl, int* il, float cd, int ci) {
    bool ins = false;
#pragma unroll
    for (int i = 0; i < KK; i++) {
        bool sw = ins || (cd < dl[i]);
        float td = sw ? dl[i] : cd;
        int   ti = sw ? il[i] : ci;
        dl[i] = sw ? cd : dl[i];
        il[i] = sw ? ci : il[i];
        cd = td; ci = ti;
        ins = sw;
    }
}

// ---------------- KNN partial: half the candidates per block --------------
// Thread = one query. Candidates staged in smem as float4(x,y,z,|x|^2).
// Hot path: predicated 8-byte push into a per-thread smem buffer. Flushes
// are warp-uniform (redux-max loop bound) and fully branch-free inside.
__global__ void __launch_bounds__(256, 2) knn_part_kernel(const float* __restrict__ x) {
    extern __shared__ char smem_raw[];
    float4* s_pts = (float4*)smem_raw;                        // 4096*16 = 64KB
    float2* s_buf = (float2*)(smem_raw + HALF_N * 16);        // 16*256*8 = 32KB

    const int b = blockIdx.z;
    const int h = blockIdx.y;
    const int tid = threadIdx.x;
    const float* __restrict__ xb = x + (size_t)b * NN * CC;

    for (int i = tid; i < HALF_N; i += 256) {
        int gi = h * HALF_N + i;
        float px = xb[gi*3+0], py = xb[gi*3+1], pz = xb[gi*3+2];
        s_pts[i] = make_float4(px, py, pz, px*px + py*py + pz*pz);
    }
    __syncthreads();

    const int q = blockIdx.x * 256 + tid;
    const float qx = xb[q*3+0], qy = xb[q*3+1], qz = xb[q*3+2];
    const float qw = qx*qx + qy*qy + qz*qz;

    float dl[KK];
    int   il[KK];
#pragma unroll
    for (int i = 0; i < KK; i++) { dl[i] = CUDART_INF_F; il[i] = 0; }
    float thr = CUDART_INF_F;
    int cnt = 0;

    for (int c0 = 0; c0 < HALF_N; c0 += GRP) {
        float d2v[GRP];
#pragma unroll
        for (int u = 0; u < GRP; u++) {
            float4 p = s_pts[c0 + u];
            float dot = fmaf(qz, p.z, fmaf(qy, p.y, qx * p.x));
            d2v[u] = fmaf(-2.0f, dot, qw + p.w);
        }
#pragma unroll
        for (int u = 0; u < GRP; u++) {
            if (d2v[u] < thr) {                      // predicated push (no branch)
                s_buf[cnt * 256 + tid] = make_float2(d2v[u], __int_as_float(c0 + u));
                cnt++;
            }
        }
        if (__any_sync(0xffffffffu, cnt >= FLUSH_AT)) {
            int mx = __reduce_max_sync(0xffffffffu, cnt);    // uniform loop bound
            for (int j = 0; j < mx; j++) {
                float2 e = s_buf[j * 256 + tid];
                float cd = (j < cnt) ? e.x : CUDART_INF_F;   // stale slots -> no-op
                int   ci = __float_as_int(e.y);
                sweep_insert(dl, il, cd, ci);                // branch-free, stable
            }
            thr = dl[KK-1];
            cnt = 0;
        }
    }
    {   // final flush
        int mx = __reduce_max_sync(0xffffffffu, cnt);
        for (int j = 0; j < mx; j++) {
            float2 e = s_buf[j * 256 + tid];
            float cd = (j < cnt) ? e.x : CUDART_INF_F;
            int   ci = __float_as_int(e.y);
            sweep_insert(dl, il, cd, ci);
        }
    }

    float2* dst = g_part + ((size_t)(b * 2 + h) * NN + q) * KK;
#pragma unroll
    for (int i = 0; i < KK; i++)
        dst[i] = make_float2(dl[i], __int_as_float(il[i] + h * HALF_N));
}

// ---------------- merge the half lists + fused moment accumulation --------
__global__ void __launch_bounds__(256) merge_stats_kernel(const float* __restrict__ x) {
    int t = blockIdx.x * blockDim.x + threadIdx.x;   // 0 .. BB*NN
    int b = t / NN;
    int q = t - b * NN;
    const float2* A = g_part + ((size_t)(b * 2 + 0) * NN + q) * KK;
    const float2* B = g_part + ((size_t)(b * 2 + 1) * NN + q) * KK;

    float ad[KK+1], bd[KK+1];
    int   ai[KK+1], bi[KK+1];
#pragma unroll
    for (int i = 0; i < KK; i++) {
        float2 ea = A[i]; ad[i] = ea.x; ai[i] = __float_as_int(ea.y);
        float2 eb = B[i]; bd[i] = eb.x; bi[i] = __float_as_int(eb.y);
    }
    ad[KK] = CUDART_INF_F; bd[KK] = CUDART_INF_F; ai[KK] = 0; bi[KK] = 0;

    int mi[KK];
    int ia = 0, ib = 0;
#pragma unroll
    for (int i = 0; i < KK; i++) {
        bool ta = ad[ia] <= bd[ib];                  // tie -> half 0 (lower idx)
        mi[i] = ta ? ai[ia] : bi[ib];
        if (ta) ia++; else ib++;
    }
    int base = (b * NN + q) * KK;
#pragma unroll
    for (int i = 0; i < KK; i++) g_knn[base + i] = mi[i];

    // fused stats: accumulate 6-moment + 21 second moments of edge vectors
    const float* __restrict__ xb = x + (size_t)b * NN * CC;
    float c0v = xb[q*3+0], c1v = xb[q*3+1], c2v = xb[q*3+2];

    float a1[6];
    float a2[21];
#pragma unroll
    for (int i = 0; i < 6; i++)  a1[i] = 0.0f;
#pragma unroll
    for (int i = 0; i < 21; i++) a2[i] = 0.0f;

#pragma unroll
    for (int kk2 = 0; kk2 < KK; kk2++) {
        const float* nb = xb + (size_t)mi[kk2] * 3;
        float v[6];
        v[0] = c0v; v[1] = c1v; v[2] = c2v;
        v[3] = nb[0] - c0v; v[4] = nb[1] - c1v; v[5] = nb[2] - c2v;
#pragma unroll
        for (int i = 0; i < 6; i++) a1[i] += v[i];
        int tt = 0;
#pragma unroll
        for (int a = 0; a < 6; a++)
#pragma unroll
            for (int bb2 = a; bb2 < 6; bb2++) { a2[tt] = fmaf(v[a], v[bb2], a2[tt]); tt++; }
    }

#pragma unroll
    for (int i = 0; i < 6; i++)
#pragma unroll
        for (int off = 16; off; off >>= 1) a1[i] += __shfl_down_sync(0xffffffffu, a1[i], off);
#pragma unroll
    for (int i = 0; i < 21; i++)
#pragma unroll
        for (int off = 16; off; off >>= 1) a2[i] += __shfl_down_sync(0xffffffffu, a2[i], off);

    if ((threadIdx.x & 31) == 0) {
#pragma unroll
        for (int i = 0; i < 6; i++)  atomicAdd(&g_m1[i], (double)a1[i]);
#pragma unroll
        for (int i = 0; i < 21; i++) atomicAdd(&g_m2[i], (double)a2[i]);
    }
}

// ---------------- finalize: fold BN into weights ---------------------------
__global__ void finalize_kernel(const float* __restrict__ W,
                                const float* __restrict__ gamma,
                                const float* __restrict__ beta) {
    int o = threadIdx.x;
    if (o >= OO) return;
    double w[6];
#pragma unroll
    for (int c = 0; c < 6; c++) w[c] = (double)W[o*6 + c];

    double s1 = 0.0;
#pragma unroll
    for (int c = 0; c < 6; c++) s1 += w[c] * g_m1[c];
    double mean = s1 / MCOUNT;

    double s2 = 0.0;
    int t = 0;
#pragma unroll
    for (int a = 0; a < 6; a++)
#pragma unroll
        for (int bb2 = a; bb2 < 6; bb2++) {
            double term = w[a] * w[bb2] * g_m2[t];
            s2 += (a == bb2) ? term : 2.0 * term;
            t++;
        }
    double Eh2 = s2 / MCOUNT;
    double var = Eh2 - mean * mean;
    double scale = (double)gamma[o] / sqrt(var + 1e-5);
    g_shift[o] = (float)((double)beta[o] - mean * scale);
#pragma unroll
    for (int c = 0; c < 6; c++) g_W2[o*6 + c] = (float)(w[c] * scale);
}

// ---------------- output: recompute h, BN+ReLU, transposed write ----------
__global__ void __launch_bounds__(256) out_kernel(const float* __restrict__ x,
                                                  float* __restrict__ out) {
    __shared__ float sv[6][256];
    const int b  = blockIdx.y;
    const int e0 = blockIdx.x * 256;       // edge offset within this batch
    const int tid = threadIdx.x;

    {   // stage 256 edge vectors
        int el = e0 + tid;
        int n  = el / KK;
        int id = g_knn[b * NK + el];
        const float* cen = x + ((size_t)b * NN + n)  * 3;
        const float* nb  = x + ((size_t)b * NN + id) * 3;
        float c0 = cen[0], c1 = cen[1], c2 = cen[2];
        sv[0][tid] = c0;
        sv[1][tid] = c1;
        sv[2][tid] = c2;
        sv[3][tid] = nb[0] - c0;
        sv[4][tid] = nb[1] - c1;
        sv[5][tid] = nb[2] - c2;
    }
    __syncthreads();

    const int lane = tid & 31;
    const int w    = tid >> 5;

    float wr[8][6], sh[8];
#pragma unroll
    for (int i = 0; i < 8; i++) {
        int o = w + 8 * i;
#pragma unroll
        for (int c = 0; c < 6; c++) wr[i][c] = g_W2[o*6 + c];
        sh[i] = g_shift[o];
    }

    float* __restrict__ outb = out + (size_t)b * OO * NK;
#pragma unroll
    for (int jj = 0; jj < 8; jj++) {
        int e = lane + 32 * jj;
        float v0 = sv[0][e], v1 = sv[1][e], v2 = sv[2][e];
        float v3 = sv[3][e], v4 = sv[4][e], v5 = sv[5][e];
#pragma unroll
        for (int i = 0; i < 8; i++) {
            int o = w + 8 * i;
            float h = sh[i];
            h = fmaf(wr[i][0], v0, h);
            h = fmaf(wr[i][1], v1, h);
            h = fmaf(wr[i][2], v2, h);
            h = fmaf(wr[i][3], v3, h);
            h = fmaf(wr[i][4], v4, h);
            h = fmaf(wr[i][5], v5, h);
            h = fmaxf(h, 0.0f);
            outb[(size_t)o * NK + (e0 + e)] = h;
        }
    }
}

// ---------------- launch ---------------------------------------------------
extern "C" void kernel_launch(void* const* d_in, const int* in_sizes, int n_in,
                              void* d_out, int out_size) {
    const float* x     = (const float*)d_in[0];
    const float* W     = (const float*)d_in[1];
    const float* gamma = (const float*)d_in[2];
    const float* beta  = (const float*)d_in[3];
    float* out = (float*)d_out;

    const int knn_smem = HALF_N * (int)sizeof(float4) + BUF_SLOTS * 256 * (int)sizeof(float2);
    cudaFuncSetAttribute(knn_part_kernel, cudaFuncAttributeMaxDynamicSharedMemorySize,
                         knn_smem);

    zero_stats_kernel<<<1, 32>>>();

    dim3 gk(NN / 256, 2, BB);                 // 32 x 2 halves x 4 batches = 256 blocks
    knn_part_kernel<<<gk, 256, knn_smem>>>(x);

    merge_stats_kernel<<<(BB * NN) / 256, 256>>>(x);

    finalize_kernel<<<1, 64>>>(W, gamma, beta);

    dim3 go(NK / 256, BB);
    out_kernel<<<go, 256>>>(x, out);
}

// round 8
// speedup vs baseline: 1.2675x; 1.2675x over previous
#include <cuda_runtime.h>
#include <math_constants.h>
#include <stdint.h>

#define BB 4
#define NN 8192
#define CC 3
#define OO 64
#define KK 20
#define NK (NN*KK)            // 163840 edges per batch
#define NEDGES (BB*NK)        // 655360 total edges
#define MCOUNT ((double)NEDGES)

#define HALF_N 4096           // candidates per split
#define BUF_SLOTS 16
#define FLUSH_AT 9            // enter group with <=8 pending, +8 pushes <= 16 slots
#define GRP 8                 // candidates per inner group

// ---------------- device scratch (no allocations allowed) ----------------
__device__ int    g_knn[NEDGES];            // neighbor index per (b,n,k)
__device__ float2 g_part[BB*2*NN*KK];       // partial top-k per (b,half,q)
__device__ double g_m1[6];                  // sum of edge vectors
__device__ double g_m2[21];                 // upper-tri sum of outer products
__device__ float  g_W2[OO*6];               // BN-folded weights
__device__ float  g_shift[OO];              // BN-folded bias

// ---------------- zero accumulators (deterministic each launch) ----------
__global__ void zero_stats_kernel() {
    int t = threadIdx.x;
    if (t < 6)  g_m1[t] = 0.0;
    if (t < 21) g_m2[t] = 0.0;
}

// ---------------- KNN partial: half the candidates per block --------------
// Thread = one query. Candidates staged in smem as float4(x,y,z,|x|^2).
// Hot path: predicated 8-byte push into a per-thread smem buffer.
// Flush (R4-proven form): branchy early-out insert; thr tightens after
// every accepted insert so most buffered entries skip the 20-step chain.
__global__ void __launch_bounds__(256, 2) knn_part_kernel(const float* __restrict__ x) {
    extern __shared__ char smem_raw[];
    float4* s_pts = (float4*)smem_raw;                        // 4096*16 = 64KB
    float2* s_buf = (float2*)(smem_raw + HALF_N * 16);        // 16*256*8 = 32KB

    const int b = blockIdx.z;
    const int h = blockIdx.y;
    const int tid = threadIdx.x;
    const float* __restrict__ xb = x + (size_t)b * NN * CC;

    for (int i = tid; i < HALF_N; i += 256) {
        int gi = h * HALF_N + i;
        float px = xb[gi*3+0], py = xb[gi*3+1], pz = xb[gi*3+2];
        s_pts[i] = make_float4(px, py, pz, px*px + py*py + pz*pz);
    }
    __syncthreads();

    const int q = blockIdx.x * 256 + tid;
    const float qx = xb[q*3+0], qy = xb[q*3+1], qz = xb[q*3+2];
    const float qw = qx*qx + qy*qy + qz*qz;

    float dl[KK];
    int   il[KK];
#pragma unroll
    for (int i = 0; i < KK; i++) { dl[i] = CUDART_INF_F; il[i] = 0; }
    float thr = CUDART_INF_F;
    int cnt = 0;

    for (int c0 = 0; c0 < HALF_N; c0 += GRP) {
        float d2v[GRP];
#pragma unroll
        for (int u = 0; u < GRP; u++) {
            float4 p = s_pts[c0 + u];
            float dot = fmaf(qz, p.z, fmaf(qy, p.y, qx * p.x));
            d2v[u] = fmaf(-2.0f, dot, qw + p.w);
        }
#pragma unroll
        for (int u = 0; u < GRP; u++) {
            if (d2v[u] < thr) {                      // predicated push (no branch)
                s_buf[cnt * 256 + tid] = make_float2(d2v[u], __int_as_float(c0 + u));
                cnt++;
            }
        }
        if (__any_sync(0xffffffffu, cnt >= FLUSH_AT)) {
            for (int j = 0; j < cnt; j++) {
                float2 e = s_buf[j * 256 + tid];
                float d = e.x;
                if (d < thr) {                       // early-out vs fresh thr
                    dl[KK-1] = d;
                    il[KK-1] = __float_as_int(e.y);
#pragma unroll
                    for (int i = KK-1; i > 0; --i) { // strict '<' keeps stability
                        bool sw = dl[i] < dl[i-1];
                        float dlo = sw ? dl[i]   : dl[i-1];
                        float dhi = sw ? dl[i-1] : dl[i];
                        int   ilo = sw ? il[i]   : il[i-1];
                        int   ihi = sw ? il[i-1] : il[i];
                        dl[i-1] = dlo; dl[i] = dhi;
                        il[i-1] = ilo; il[i] = ihi;
                    }
                    thr = dl[KK-1];
                }
            }
            cnt = 0;
        }
    }
    // final flush
    for (int j = 0; j < cnt; j++) {
        float2 e = s_buf[j * 256 + tid];
        float d = e.x;
        if (d < thr) {
            dl[KK-1] = d;
            il[KK-1] = __float_as_int(e.y);
#pragma unroll
            for (int i = KK-1; i > 0; --i) {
                bool sw = dl[i] < dl[i-1];
                float dlo = sw ? dl[i]   : dl[i-1];
                float dhi = sw ? dl[i-1] : dl[i];
                int   ilo = sw ? il[i]   : il[i-1];
                int   ihi = sw ? il[i-1] : il[i];
                dl[i-1] = dlo; dl[i] = dhi;
                il[i-1] = ilo; il[i] = ihi;
            }
            thr = dl[KK-1];
        }
    }

    float2* dst = g_part + ((size_t)(b * 2 + h) * NN + q) * KK;
#pragma unroll
    for (int i = 0; i < KK; i++)
        dst[i] = make_float2(dl[i], __int_as_float(il[i] + h * HALF_N));
}

// ---------------- merge the half lists + fused moment accumulation --------
__global__ void __launch_bounds__(256) merge_stats_kernel(const float* __restrict__ x) {
    int t = blockIdx.x * blockDim.x + threadIdx.x;   // 0 .. BB*NN
    int b = t / NN;
    int q = t - b * NN;
    const float2* A = g_part + ((size_t)(b * 2 + 0) * NN + q) * KK;
    const float2* B = g_part + ((size_t)(b * 2 + 1) * NN + q) * KK;

    float ad[KK+1], bd[KK+1];
    int   ai[KK+1], bi[KK+1];
#pragma unroll
    for (int i = 0; i < KK; i++) {
        float2 ea = A[i]; ad[i] = ea.x; ai[i] = __float_as_int(ea.y);
        float2 eb = B[i]; bd[i] = eb.x; bi[i] = __float_as_int(eb.y);
    }
    ad[KK] = CUDART_INF_F; bd[KK] = CUDART_INF_F; ai[KK] = 0; bi[KK] = 0;

    int mi[KK];
    int ia = 0, ib = 0;
#pragma unroll
    for (int i = 0; i < KK; i++) {
        bool ta = ad[ia] <= bd[ib];                  // tie -> half 0 (lower idx)
        mi[i] = ta ? ai[ia] : bi[ib];
        if (ta) ia++; else ib++;
    }
    int base = (b * NN + q) * KK;
#pragma unroll
    for (int i = 0; i < KK; i++) g_knn[base + i] = mi[i];

    // fused stats: accumulate 6 first + 21 second moments of edge vectors
    const float* __restrict__ xb = x + (size_t)b * NN * CC;
    float c0v = xb[q*3+0], c1v = xb[q*3+1], c2v = xb[q*3+2];

    float a1[6];
    float a2[21];
#pragma unroll
    for (int i = 0; i < 6; i++)  a1[i] = 0.0f;
#pragma unroll
    for (int i = 0; i < 21; i++) a2[i] = 0.0f;

#pragma unroll
    for (int kk2 = 0; kk2 < KK; kk2++) {
        const float* nb = xb + (size_t)mi[kk2] * 3;
        float v[6];
        v[0] = c0v; v[1] = c1v; v[2] = c2v;
        v[3] = nb[0] - c0v; v[4] = nb[1] - c1v; v[5] = nb[2] - c2v;
#pragma unroll
        for (int i = 0; i < 6; i++) a1[i] += v[i];
        int tt = 0;
#pragma unroll
        for (int a = 0; a < 6; a++)
#pragma unroll
            for (int bb2 = a; bb2 < 6; bb2++) { a2[tt] = fmaf(v[a], v[bb2], a2[tt]); tt++; }
    }

#pragma unroll
    for (int i = 0; i < 6; i++)
#pragma unroll
        for (int off = 16; off; off >>= 1) a1[i] += __shfl_down_sync(0xffffffffu, a1[i], off);
#pragma unroll
    for (int i = 0; i < 21; i++)
#pragma unroll
        for (int off = 16; off; off >>= 1) a2[i] += __shfl_down_sync(0xffffffffu, a2[i], off);

    if ((threadIdx.x & 31) == 0) {
#pragma unroll
        for (int i = 0; i < 6; i++)  atomicAdd(&g_m1[i], (double)a1[i]);
#pragma unroll
        for (int i = 0; i < 21; i++) atomicAdd(&g_m2[i], (double)a2[i]);
    }
}

// ---------------- finalize: fold BN into weights ---------------------------
__global__ void finalize_kernel(const float* __restrict__ W,
                                const float* __restrict__ gamma,
                                const float* __restrict__ beta) {
    int o = threadIdx.x;
    if (o >= OO) return;
    double w[6];
#pragma unroll
    for (int c = 0; c < 6; c++) w[c] = (double)W[o*6 + c];

    double s1 = 0.0;
#pragma unroll
    for (int c = 0; c < 6; c++) s1 += w[c] * g_m1[c];
    double mean = s1 / MCOUNT;

    double s2 = 0.0;
    int t = 0;
#pragma unroll
    for (int a = 0; a < 6; a++)
#pragma unroll
        for (int bb2 = a; bb2 < 6; bb2++) {
            double term = w[a] * w[bb2] * g_m2[t];
            s2 += (a == bb2) ? term : 2.0 * term;
            t++;
        }
    double Eh2 = s2 / MCOUNT;
    double var = Eh2 - mean * mean;
    double scale = (double)gamma[o] / sqrt(var + 1e-5);
    g_shift[o] = (float)((double)beta[o] - mean * scale);
#pragma unroll
    for (int c = 0; c < 6; c++) g_W2[o*6 + c] = (float)(w[c] * scale);
}

// ---------------- output: recompute h, BN+ReLU, transposed write ----------
__global__ void __launch_bounds__(256) out_kernel(const float* __restrict__ x,
                                                  float* __restrict__ out) {
    __shared__ float sv[6][256];
    const int b  = blockIdx.y;
    const int e0 = blockIdx.x * 256;       // edge offset within this batch
    const int tid = threadIdx.x;

    {   // stage 256 edge vectors
        int el = e0 + tid;
        int n  = el / KK;
        int id = g_knn[b * NK + el];
        const float* cen = x + ((size_t)b * NN + n)  * 3;
        const float* nb  = x + ((size_t)b * NN + id) * 3;
        float c0 = cen[0], c1 = cen[1], c2 = cen[2];
        sv[0][tid] = c0;
        sv[1][tid] = c1;
        sv[2][tid] = c2;
        sv[3][tid] = nb[0] - c0;
        sv[4][tid] = nb[1] - c1;
        sv[5][tid] = nb[2] - c2;
    }
    __syncthreads();

    const int lane = tid & 31;
    const int w    = tid >> 5;

    float wr[8][6], sh[8];
#pragma unroll
    for (int i = 0; i < 8; i++) {
        int o = w + 8 * i;
#pragma unroll
        for (int c = 0; c < 6; c++) wr[i][c] = g_W2[o*6 + c];
        sh[i] = g_shift[o];
    }

    float* __restrict__ outb = out + (size_t)b * OO * NK;
#pragma unroll
    for (int jj = 0; jj < 8; jj++) {
        int e = lane + 32 * jj;
        float v0 = sv[0][e], v1 = sv[1][e], v2 = sv[2][e];
        float v3 = sv[3][e], v4 = sv[4][e], v5 = sv[5][e];
#pragma unroll
        for (int i = 0; i < 8; i++) {
            int o = w + 8 * i;
            float h = sh[i];
            h = fmaf(wr[i][0], v0, h);
            h = fmaf(wr[i][1], v1, h);
            h = fmaf(wr[i][2], v2, h);
            h = fmaf(wr[i][3], v3, h);
            h = fmaf(wr[i][4], v4, h);
            h = fmaf(wr[i][5], v5, h);
            h = fmaxf(h, 0.0f);
            outb[(size_t)o * NK + (e0 + e)] = h;
        }
    }
}

// ---------------- launch ---------------------------------------------------
extern "C" void kernel_launch(void* const* d_in, const int* in_sizes, int n_in,
                              void* d_out, int out_size) {
    const float* x     = (const float*)d_in[0];
    const float* W     = (const float*)d_in[1];
    const float* gamma = (const float*)d_in[2];
    const float* beta  = (const float*)d_in[3];
    float* out = (float*)d_out;

    const int knn_smem = HALF_N * (int)sizeof(float4) + BUF_SLOTS * 256 * (int)sizeof(float2);
    cudaFuncSetAttribute(knn_part_kernel, cudaFuncAttributeMaxDynamicSharedMemorySize,
                         knn_smem);

    zero_stats_kernel<<<1, 32>>>();

    dim3 gk(NN / 256, 2, BB);                 // 32 x 2 halves x 4 batches = 256 blocks
    knn_part_kernel<<<gk, 256, knn_smem>>>(x);

    merge_stats_kernel<<<(BB * NN) / 256, 256>>>(x);

    finalize_kernel<<<1, 64>>>(W, gamma, beta);

    dim3 go(NK / 256, BB);
    out_kernel<<<go, 256>>>(x, out);
}